// round 9
// baseline (speedup 1.0000x reference)
#include <cuda_runtime.h>
#include <math.h>

// SpikingLayer — bit-exact replication of the JAX/XLA reference (r6 PASSED,
// rel_err 5.049e-4 @ 1961us). This revision keeps the arithmetic sequence
// bit-identical and restructures for speed:
//   - conv: divergent per-bit while-loops (branch machinery ~1500 cyc/step)
//     replaced by per-synapse spike-age queues (u8 ring in local mem) and ONE
//     uniform-bound branchless loop. Same FADD fold, oldest-first, same taps.
//   - buf update: rs table reads via aligned LDS.128 from 4 rotation-shifted
//     doubled tables (25 float4 loads/step instead of 50 LDS.64).
//   - __any_sync skip of the update when no lane fired (exact no-ops skipped).

#define T_STEPS 1024
#define BATCH   16
#define NSYN    2
#define NNEU    2048
#define BN      (BATCH * NNEU)          // 32768 neurons
#define TSTRIDE (BATCH * NSYN * NNEU)   // 65536 floats per timestep
#define PF      4                       // prefetch depth (divides 100 and 24)

__global__ __launch_bounds__(128, 2)
void spiking_layer_exact2(const float* __restrict__ in,
                          const float* __restrict__ epsp,   // (2, 100)
                          const float* __restrict__ refk,   // (100,)
                          float* __restrict__ out)
{
    // K tables padded to 128 with zeros (index 127 = exact no-op tap).
    __shared__ __align__(16) float K0[128];
    __shared__ __align__(16) float K1[128];
    // RSD[r][i] = rs[(i + r) % 100], i < 200 (doubled, rotation-shifted so a
    // 16B-aligned float4 read covers any window start). rs[k]=-refk[k+1], rs[99]=0.
    __shared__ __align__(16) float RSD[4][200];

    const int tid = threadIdx.x;
    {
        int j = tid;                       // 128 threads, one element each
        K0[j] = (j < 100) ? epsp[j] : 0.0f;
        K1[j] = (j < 100) ? epsp[100 + j] : 0.0f;
    }
    for (int i = tid; i < 4 * 200; i += 128) {
        int rr = i / 200, ii = i % 200;
        int k = (ii + rr) % 100;
        RSD[rr][ii] = (k < 99) ? -refk[k + 1] : 0.0f;
    }
    __syncthreads();

    const int g = blockIdx.x * 128 + tid;       // neuron id
    const int b = g >> 11;
    const int n = g & (NNEU - 1);
    const float* p0 = in + (size_t)b * (NSYN * NNEU) + n;  // synapse 0
    const float* p1 = p0 + NNEU;                            // synapse 1
    float* po = out + g;

    // refractory buffer: 100 slots as 50 packed f32x2 pairs (lo = even slot)
    unsigned long long bufp[50];
#pragma unroll
    for (int m = 0; m < 50; m++) bufp[m] = 0ull;

    // spike-age queues: ring of u8 timestamps (t & 255) per synapse.
    // Entries beyond len are garbage — guarded in the conv loop.
    unsigned char q0[128], q1[128];
    int h0 = 0, tq0 = 0, len0 = 0; int head0 = 0;
    int h1 = 0, tq1 = 0, len1 = 0; int head1 = 0;

    float x0b[PF], x1b[PF];
#pragma unroll
    for (int i = 0; i < PF; i++) {
        x0b[i] = __ldcs(p0 + (size_t)i * TSTRIDE);
        x1b[i] = __ldcs(p1 + (size_t)i * TSTRIDE);
    }

    auto step = [&](int t, int c) {
        const int i4 = c & (PF - 1);
        const float x0 = x0b[i4];
        const float x1 = x1b[i4];
        if (t + PF < T_STEPS) {
            x0b[i4] = __ldcs(p0 + (size_t)(t + PF) * TSTRIDE);
            x1b[i4] = __ldcs(p1 + (size_t)(t + PF) * TSTRIDE);
        }
        const int tb8 = t & 255;

        // pop expired head (lag >= 100), branchless; at most one per step.
        {
            int lagh = (tb8 - head0) & 255;
            int pop  = (len0 > 0) & (lagh >= 100);
            int nxt  = q0[(h0 + 1) & 127];
            h0 += pop; len0 -= pop;
            head0 = pop ? nxt : head0;
        }
        {
            int lagh = (tb8 - head1) & 255;
            int pop  = (len1 > 0) & (lagh >= 100);
            int nxt  = q1[(h1 + 1) & 127];
            h1 += pop; len1 -= pop;
            head1 = pop ? nxt : head1;
        }

        // push current spikes (store unconditional — slot is beyond tail and
        // guarded; tail/len advance only on spike).
        const int s0 = (x0 != 0.0f);
        const int s1 = (x1 != 0.0f);
        q0[tq0 & 127] = (unsigned char)tb8;
        q1[tq1 & 127] = (unsigned char)tb8;
        head0 = (len0 == 0 && s0) ? tb8 : head0;
        head1 = (len1 == 0 && s1) ? tb8 : head1;
        tq0 += s0; len0 += s0;
        tq1 += s1; len1 += s1;

        // EPSP conv: fold set taps oldest-first with plain FADD — identical
        // rounding sequence to the r6 passing kernel (queue iterates oldest
        // to newest = lag descending; invalid lanes fold K[127]=0, exact no-op).
        float a0 = 0.0f, a1 = 0.0f;
        {
            const int ml = (len0 > len1) ? len0 : len1;
            const int iters = __reduce_max_sync(0xffffffffu, ml);
#pragma unroll 1
            for (int i = 0; i < iters; ++i) {
                int ts0 = q0[(h0 + i) & 127];
                int ts1 = q1[(h1 + i) & 127];
                int g0 = (tb8 - ts0) & 255;
                int g1 = (tb8 - ts1) & 255;
                g0 = (i < len0) ? g0 : 127;
                g1 = (i < len1) ? g1 : 127;
                a0 = __fadd_rn(a0, K0[g0]);
                a1 = __fadd_rn(a1, K1[g1]);
            }
        }
        const float vt = __fadd_rn(a0, a1);   // vmem_syn.sum(axis=1)

        // read refractory accumulator for this step (slot c, compile-time)
        float bacc;
        {
            unsigned long long pr = bufp[c >> 1];
            unsigned int u = (c & 1) ? (unsigned int)(pr >> 32) : (unsigned int)pr;
            bacc = __uint_as_float(u);
        }
        const float v = __fadd_rn(vt, bacc);  // v_eff = v_t + buf[0]

        // spike function, op-for-op vs reference
        const float nf   = floorf(fmaxf(v, 0.0f));
        const float e    = expf(__fmul_rn(fabsf(__fadd_rn(v, -1.0f)), -2.0f));
        const float sg   = __fmul_rn(2.0f, e);
        const float term = __fmul_rn(sg, v);
        const float nout = __fadd_rn(__fadd_rn(nf, -term), term);

        __stcs(po + (size_t)t * BN, nout);

        // zero slot c (becomes the slot for time t+100; rs[99]=0)
        bufp[c >> 1] &= (c & 1) ? 0x00000000FFFFFFFFull : 0xFFFFFFFF00000000ull;

        // buf update: slot s += fl(nout * rs[(s-c-1) mod 100]) as packed f32x2.
        // Skipped entirely when no lane fired (all adds exact no-ops).
        if (__any_sync(0xffffffffu, nout != 0.0f)) {
            unsigned long long n2;
            asm("mov.b64 %0, {%1, %2};" : "=l"(n2) : "f"(nout), "f"(nout));
            const int s0i = 99 - c;            // (-c-1) mod 100
            const int rr  = s0i & 3;
            const float* T = &RSD[rr][s0i - rr];   // 16B-aligned sweep base
#pragma unroll
            for (int j = 0; j < 25; ++j) {
                const float4 rq = *(const float4*)(T + 4 * j);
                unsigned long long rsA, rsB, pA, pB, nA, nB;
                asm("mov.b64 %0, {%1, %2};" : "=l"(rsA) : "f"(rq.x), "f"(rq.y));
                asm("mov.b64 %0, {%1, %2};" : "=l"(rsB) : "f"(rq.z), "f"(rq.w));
                asm("mul.rn.f32x2 %0, %1, %2;" : "=l"(pA) : "l"(n2), "l"(rsA));
                asm("add.rn.f32x2 %0, %1, %2;" : "=l"(nA) : "l"(bufp[2 * j]), "l"(pA));
                bufp[2 * j] = nA;
                asm("mul.rn.f32x2 %0, %1, %2;" : "=l"(pB) : "l"(n2), "l"(rsB));
                asm("add.rn.f32x2 %0, %1, %2;" : "=l"(nB) : "l"(bufp[2 * j + 1]), "l"(pB));
                bufp[2 * j + 1] = nB;
            }
        }
    };

#pragma unroll 1
    for (int blk = 0; blk < 10; ++blk) {
        const int tb = blk * 100;
#pragma unroll
        for (int i = 0; i < 100; ++i) step(tb + i, i);
    }
#pragma unroll
    for (int i = 0; i < 24; ++i) step(1000 + i, i);
}

extern "C" void kernel_launch(void* const* d_in, const int* in_sizes, int n_in,
                              void* d_out, int out_size)
{
    const float* spikes = (const float*)d_in[0];
    const float* epsp   = (const float*)d_in[1];
    const float* refk   = (const float*)d_in[2];
    float* out = (float*)d_out;

    spiking_layer_exact2<<<BN / 128, 128>>>(spikes, epsp, refk, out);
}